// round 13
// baseline (speedup 1.0000x reference)
#include <cuda_runtime.h>
#include <cuda_fp16.h>
#include <cstdint>

#define BATCH 2
#define SEQ 2048
#define DMODEL 1024
#define NH 16
#define HD 64
#define BH (BATCH * NH)
#define N_QKV (3 * DMODEL)
#define GK 1024

// Scratch (allocation-free). All operand buffers are fp16.
__device__ __half g_q[BH * SEQ * HD];          // [bh][s][d], pre-scaled by 0.125
__device__ __half g_k[BH * SEQ * HD];          // [bh][s][d]
__device__ __half g_v[BH * SEQ * HD];          // [bh][s][d]  (row-major now)
__device__ __half g_att[BATCH * SEQ * DMODEL]; // attn output
__device__ __half g_xt[BATCH * SEQ * GK];      // X converted
__device__ __half g_wqkv_t[N_QKV * GK];        // [N=3072][K=1024]
__device__ __half g_wo_t[DMODEL * GK];         // [N=1024][K=1024]

__device__ __forceinline__ uint32_t pack_h2(float lo, float hi) {
    __half2 h = __floats2half2_rn(lo, hi);
    return *reinterpret_cast<uint32_t*>(&h);
}

__device__ __forceinline__ void mma_f16(
    float& c0, float& c1, float& c2, float& c3,
    uint32_t a0, uint32_t a1, uint32_t a2, uint32_t a3,
    uint32_t b0, uint32_t b1)
{
    asm volatile(
        "mma.sync.aligned.m16n8k16.row.col.f32.f16.f16.f32 "
        "{%0,%1,%2,%3}, {%4,%5,%6,%7}, {%8,%9}, {%0,%1,%2,%3};"
        : "+f"(c0), "+f"(c1), "+f"(c2), "+f"(c3)
        : "r"(a0), "r"(a1), "r"(a2), "r"(a3), "r"(b0), "r"(b1));
}

__device__ __forceinline__ void ldsm_x4(
    uint32_t& r0, uint32_t& r1, uint32_t& r2, uint32_t& r3, uint32_t saddr)
{
    asm volatile(
        "ldmatrix.sync.aligned.m8n8.x4.shared.b16 {%0,%1,%2,%3}, [%4];"
        : "=r"(r0), "=r"(r1), "=r"(r2), "=r"(r3) : "r"(saddr));
}

__device__ __forceinline__ void ldsm_x4_trans(
    uint32_t& r0, uint32_t& r1, uint32_t& r2, uint32_t& r3, uint32_t saddr)
{
    asm volatile(
        "ldmatrix.sync.aligned.m8n8.x4.trans.shared.b16 {%0,%1,%2,%3}, [%4];"
        : "=r"(r0), "=r"(r1), "=r"(r2), "=r"(r3) : "r"(saddr));
}

__device__ __forceinline__ void cp_async16(uint32_t smem_addr, const void* gptr) {
    asm volatile("cp.async.cg.shared.global [%0], [%1], 16;"
                 :: "r"(smem_addr), "l"(gptr) : "memory");
}
#define CP_COMMIT() asm volatile("cp.async.commit_group;" ::: "memory")
#define CP_WAIT(n)  asm volatile("cp.async.wait_group %0;" :: "n"(n) : "memory")

// ===========================================================================
// Transpose+convert: out[c][r] = h(in[r][c]), in is R x C row-major fp32
// ===========================================================================
__global__ void transpose_h_kernel(const float* __restrict__ in,
                                   __half* __restrict__ out, int R, int C)
{
    __shared__ float t[32][33];
    int c0 = blockIdx.x * 32, r0 = blockIdx.y * 32;
    int x = threadIdx.x, y = threadIdx.y;  // block (32, 8)
    #pragma unroll
    for (int i = 0; i < 32; i += 8)
        t[y + i][x] = in[(size_t)(r0 + y + i) * C + c0 + x];
    __syncthreads();
    #pragma unroll
    for (int i = 0; i < 32; i += 8)
        out[(size_t)(c0 + y + i) * R + r0 + x] = __float2half_rn(t[x][y + i]);
}

// ===========================================================================
// Elementwise convert fp32 -> fp16, vectorized
// ===========================================================================
__global__ void convert_x_kernel(const float* __restrict__ in,
                                 __half* __restrict__ out)
{
    const int i = (blockIdx.x * 256 + threadIdx.x) * 4;
    float4 v = *reinterpret_cast<const float4*>(in + i);
    uint2 u;
    u.x = pack_h2(v.x, v.y);
    u.y = pack_h2(v.z, v.w);
    *reinterpret_cast<uint2*>(out + i) = u;
}

// ===========================================================================
// fp16 mma.sync GEMM, 3-stage cp.async pipeline, KC=64, ldmatrix fragments.
// C[4096, N] = A @ Bt^T + bias.  CTA 128x128, 8 warps (4M x 2N), warp m32xn64.
// EPI 0: scatter q/k/v (all row-major, packed 32-bit).  EPI 1: fp32 write.
// ===========================================================================
#define KCH 64
#define NKCH (GK / KCH)                  // 16
#define NSTAGE 3
#define RS_H 72                          // smem row stride in halfs (64 + pad)
#define OP_BYTES (128 * RS_H * 2)        // 18432 per operand per stage
#define STAGE_BYTES_G (2 * OP_BYTES)     // 36864 (A then B)
#define TC_SMEM_BYTES (NSTAGE * STAGE_BYTES_G)  // 110592

template<int EPI>
__global__ __launch_bounds__(256, 2) void tc_gemm_kernel(
    const __half* __restrict__ A, const __half* __restrict__ Bt,
    const float* __restrict__ bias, float* __restrict__ C)
{
    extern __shared__ uint32_t sm[];
    uint32_t smb;
    asm("{ .reg .u64 t; cvta.to.shared.u64 t, %1; cvt.u32.u64 %0, t; }"
        : "=r"(smb) : "l"(sm));

    const int tid = threadIdx.x;
    const int wid = tid >> 5, lane = tid & 31;
    const int grp = lane >> 2, tig = lane & 3;
    const int wm = wid >> 1, wn = wid & 1;
    const int m0 = blockIdx.y * 128;
    const int n0 = blockIdx.x * 128;

    const __half* Ag = A + (size_t)m0 * GK;
    const __half* Bg = Bt + (size_t)n0 * GK;

    // ldmatrix per-lane row/col mapping
    const int lt = lane >> 3, le = lane & 7;
    const int rA = le + (lt & 1) * 8;          // A: tiles (m8, m8+8) x (k0-7, k8-15)
    const int cA = (lt >> 1) * 8;
    const int rB = le + (lt >> 1) * 8;         // B: tiles (n8, n8+8) x (k0-7, k8-15)
    const int cB = (lt & 1) * 8;

    // cp.async coords: 128 rows x 128B per operand per chunk; 4x16B per thread
    const int lr = tid >> 1;            // row 0..127
    const int lcb = (tid & 1) * 4;      // chunk base 0 or 4 (8-half chunks)

    float acc[2][8][4];
    #pragma unroll
    for (int i = 0; i < 2; i++)
        #pragma unroll
        for (int j = 0; j < 8; j++)
            #pragma unroll
            for (int q = 0; q < 4; q++) acc[i][j][q] = 0.0f;

    // prologue: chunks 0..NSTAGE-2 into stages 0..NSTAGE-2 (one group each)
    #pragma unroll
    for (int p = 0; p < NSTAGE - 1; p++) {
        const uint32_t asmp = smb + p * STAGE_BYTES_G;
        const uint32_t bsmp = asmp + OP_BYTES;
        const __half* ap = Ag + p * KCH;
        const __half* bp = Bg + p * KCH;
        #pragma unroll
        for (int i = 0; i < 4; i++) {
            const int c = lcb + i;
            cp_async16(asmp + (lr * RS_H + c * 8) * 2, ap + (size_t)lr * GK + c * 8);
            cp_async16(bsmp + (lr * RS_H + c * 8) * 2, bp + (size_t)lr * GK + c * 8);
        }
        CP_COMMIT();
    }

    for (int kc = 0; kc < NKCH; kc++) {
        if (kc < NKCH - 1) { CP_WAIT(NSTAGE - 2); }
        else               { CP_WAIT(0); }
        __syncthreads();   // chunk kc visible; compute kc-1 done by all warps

        // prefetch chunk kc+NSTAGE-1 into its stage (freed by barrier above)
        if (kc + NSTAGE - 1 < NKCH) {
            const int st = (kc + NSTAGE - 1) % NSTAGE;
            const uint32_t asmx = smb + st * STAGE_BYTES_G;
            const uint32_t bsmx = asmx + OP_BYTES;
            const __half* an = Ag + (kc + NSTAGE - 1) * KCH;
            const __half* bn = Bg + (kc + NSTAGE - 1) * KCH;
            #pragma unroll
            for (int i = 0; i < 4; i++) {
                const int c = lcb + i;
                cp_async16(asmx + (lr * RS_H + c * 8) * 2, an + (size_t)lr * GK + c * 8);
                cp_async16(bsmx + (lr * RS_H + c * 8) * 2, bn + (size_t)lr * GK + c * 8);
            }
            CP_COMMIT();
        }

        const uint32_t abase = smb + (kc % NSTAGE) * STAGE_BYTES_G;
        const uint32_t bbase = abase + OP_BYTES;

        #pragma unroll
        for (int ks = 0; ks < 4; ks++) {          // 4 x k16 per KC=64
            const int kh = ks * 16;               // half offset
            uint32_t af[2][4];
            #pragma unroll
            for (int mt = 0; mt < 2; mt++)
                ldsm_x4(af[mt][0], af[mt][1], af[mt][2], af[mt][3],
                        abase + ((wm * 32 + mt * 16 + rA) * RS_H + kh + cA) * 2);
            uint32_t bf[4][4];
            #pragma unroll
            for (int p = 0; p < 4; p++)
                ldsm_x4(bf[p][0], bf[p][1], bf[p][2], bf[p][3],
                        bbase + ((wn * 64 + p * 16 + rB) * RS_H + kh + cB) * 2);
            #pragma unroll
            for (int nt = 0; nt < 8; nt++) {
                const uint32_t b0 = bf[nt >> 1][(nt & 1) * 2];
                const uint32_t b1 = bf[nt >> 1][(nt & 1) * 2 + 1];
                #pragma unroll
                for (int mt = 0; mt < 2; mt++)
                    mma_f16(acc[mt][nt][0], acc[mt][nt][1],
                            acc[mt][nt][2], acc[mt][nt][3],
                            af[mt][0], af[mt][1], af[mt][2], af[mt][3],
                            b0, b1);
            }
        }
    }

    #pragma unroll
    for (int mt = 0; mt < 2; mt++) {
        #pragma unroll
        for (int half = 0; half < 2; half++) {
            const int m = m0 + wm * 32 + mt * 16 + grp + half * 8;
            #pragma unroll
            for (int nt = 0; nt < 8; nt++) {
                const int n = n0 + wn * 64 + nt * 8 + tig * 2;   // even; n,n+1 pair
                const float v0 = acc[mt][nt][half * 2 + 0] + __ldg(&bias[n]);
                const float v1 = acc[mt][nt][half * 2 + 1] + __ldg(&bias[n + 1]);
                if (EPI == 0) {
                    const int b = m >> 11;
                    const int srow = m & (SEQ - 1);
                    const int h = n / 192;
                    const int r = n - h * 192;
                    const int which = r >> 6;
                    const int dd = r & 63;                      // even
                    const int bh = b * NH + h;
                    const size_t idx = ((size_t)bh * SEQ + srow) * HD + dd;
                    if (which == 0)
                        *reinterpret_cast<uint32_t*>(&g_q[idx]) =
                            pack_h2(v0 * 0.125f, v1 * 0.125f);
                    else if (which == 1)
                        *reinterpret_cast<uint32_t*>(&g_k[idx]) = pack_h2(v0, v1);
                    else
                        *reinterpret_cast<uint32_t*>(&g_v[idx]) = pack_h2(v0, v1);
                } else {
                    *reinterpret_cast<float2*>(&C[(size_t)m * DMODEL + n]) =
                        make_float2(v0, v1);
                }
            }
        }
    }
}

// ===========================================================================
// fp16 tensor-core causal flash attention, 3-stage cp.async K/V pipeline,
// ldmatrix fragments (V via ldmatrix.trans from row-major [s][d]).
// CTA: 128 q-rows x 64-key tiles, 8 warps (warp m16xn64).  Grid: LPT order.
// ===========================================================================
#define RS_A 72                            // smem row stride in halfs
#define AT_OP_BYTES (64 * RS_A * 2)        // 9216 per operand tile
#define AT_PAIR_BYTES (2 * AT_OP_BYTES)    // K then V = 18432 per stage
#define NSTAGE_A 3
#define AT_SMEM_BYTES (NSTAGE_A * AT_PAIR_BYTES)  // 55296

__global__ __launch_bounds__(256, 2) void attn_tc_kernel()
{
    extern __shared__ uint32_t sm[];
    uint32_t smb;
    asm("{ .reg .u64 t; cvta.to.shared.u64 t, %1; cvt.u32.u64 %0, t; }"
        : "=r"(smb) : "l"(sm));

    const int tid = threadIdx.x;
    const int wid = tid >> 5, lane = tid & 31;
    const int grp = lane >> 2, tig = lane & 3;
    const int bid = blockIdx.x;
    const int qt = (SEQ / 128 - 1) - (bid >> 5);   // heavy tiles first
    const int bh = bid & 31;
    const int qbase = qt * 128;
    const int wrow = wid * 16;

    const __half* __restrict__ Qu = g_q + ((size_t)bh * SEQ + qbase + wrow) * HD;
    const __half* __restrict__ Ku = g_k + (size_t)bh * SEQ * HD;
    const __half* __restrict__ Vu = g_v + (size_t)bh * SEQ * HD;   // [s][d]

    // ldmatrix lane mappings
    const int lt = lane >> 3, le = lane & 7;
    const int rB = le + (lt >> 1) * 8;             // K (non-trans): n-rows
    const int cB = (lt & 1) * 8;
    const int rV = (lt & 1) * 8 + le;              // V (trans): s-rows (k dim)
    const int cV = (lt >> 1) * 8;                  // d-cols (n dim)

    // ---- Q fragments straight from global (fp16, pre-scaled) ----
    uint32_t aq[4][4];
    #pragma unroll
    for (int kb = 0; kb < 4; kb++) {
        aq[kb][0] = *reinterpret_cast<const uint32_t*>(Qu + grp * HD + kb * 16 + 2 * tig);
        aq[kb][1] = *reinterpret_cast<const uint32_t*>(Qu + (grp + 8) * HD + kb * 16 + 2 * tig);
        aq[kb][2] = *reinterpret_cast<const uint32_t*>(Qu + grp * HD + kb * 16 + 8 + 2 * tig);
        aq[kb][3] = *reinterpret_cast<const uint32_t*>(Qu + (grp + 8) * HD + kb * 16 + 8 + 2 * tig);
    }

    float o[8][4];
    #pragma unroll
    for (int nt = 0; nt < 8; nt++)
        #pragma unroll
        for (int q = 0; q < 4; q++) o[nt][q] = 0.0f;
    float m0r = -1e30f, m1r = -1e30f, l0 = 0.0f, l1 = 0.0f;

    const int nkt = 2 * qt + 2;

    // cp.async coords: 64 rows x 128B per operand; 2x16B per thread per operand
    const int cr = tid >> 2;            // row 0..63
    const int ca = tid & 3;             // chunks ca and ca+4

    // prologue: tiles 0..NSTAGE_A-2 (nkt >= 2 always)
    #pragma unroll
    for (int p = 0; p < NSTAGE_A - 1; p++) {
        const uint32_t ksm = smb + p * AT_PAIR_BYTES;
        const uint32_t vsm = ksm + AT_OP_BYTES;
        const __half* kg = Ku + (size_t)p * 64 * HD;
        const __half* vg = Vu + (size_t)p * 64 * HD;
        #pragma unroll
        for (int i = 0; i < 2; i++) {
            const int c = ca + i * 4;
            cp_async16(ksm + (cr * RS_A + c * 8) * 2, kg + (size_t)cr * HD + c * 8);
            cp_async16(vsm + (cr * RS_A + c * 8) * 2, vg + (size_t)cr * HD + c * 8);
        }
        CP_COMMIT();
    }

    for (int kt = 0; kt < nkt; kt++) {
        if (kt < nkt - 1) { CP_WAIT(NSTAGE_A - 2); }
        else              { CP_WAIT(0); }
        __syncthreads();   // tile kt resident; compute kt-1 done by all warps

        if (kt + NSTAGE_A - 1 < nkt) {
            const int st = (kt + NSTAGE_A - 1) % NSTAGE_A;
            const uint32_t ksm = smb + st * AT_PAIR_BYTES;
            const uint32_t vsm = ksm + AT_OP_BYTES;
            const __half* kg = Ku + (size_t)(kt + NSTAGE_A - 1) * 64 * HD;
            const __half* vg = Vu + (size_t)(kt + NSTAGE_A - 1) * 64 * HD;
            #pragma unroll
            for (int i = 0; i < 2; i++) {
                const int c = ca + i * 4;
                cp_async16(ksm + (cr * RS_A + c * 8) * 2, kg + (size_t)cr * HD + c * 8);
                cp_async16(vsm + (cr * RS_A + c * 8) * 2, vg + (size_t)cr * HD + c * 8);
            }
            CP_COMMIT();
        }

        const uint32_t kbase_b = smb + (kt % NSTAGE_A) * AT_PAIR_BYTES;
        const uint32_t vbase_b = kbase_b + AT_OP_BYTES;

        // ---- S = Q K^T : 4 k16-blocks x 8 n-tiles ----
        float s[8][4];
        #pragma unroll
        for (int nt = 0; nt < 8; nt++)
            #pragma unroll
            for (int q = 0; q < 4; q++) s[nt][q] = 0.0f;

        #pragma unroll
        for (int kb = 0; kb < 4; kb++) {
            uint32_t kf[4][4];
            #pragma unroll
            for (int p = 0; p < 4; p++)
                ldsm_x4(kf[p][0], kf[p][1], kf[p][2], kf[p][3],
                        kbase_b + ((p * 16 + rB) * RS_A + kb * 16 + cB) * 2);
            #pragma unroll
            for (int nt = 0; nt < 8; nt++) {
                const uint32_t b0 = kf[nt >> 1][(nt & 1) * 2];
                const uint32_t b1 = kf[nt >> 1][(nt & 1) * 2 + 1];
                mma_f16(s[nt][0], s[nt][1], s[nt][2], s[nt][3],
                        aq[kb][0], aq[kb][1], aq[kb][2], aq[kb][3], b0, b1);
            }
        }

        // ---- causal mask (last two tiles only) ----
        if (kt >= 2 * qt) {
            const int row0 = qbase + wrow + grp;
            const int colb = kt * 64 + tig * 2;
            #pragma unroll
            for (int nt = 0; nt < 8; nt++) {
                const int c = colb + nt * 8;
                if (c > row0)         s[nt][0] = -1e30f;
                if (c + 1 > row0)     s[nt][1] = -1e30f;
                if (c > row0 + 8)     s[nt][2] = -1e30f;
                if (c + 1 > row0 + 8) s[nt][3] = -1e30f;
            }
        }

        // ---- online softmax (2 rows per thread, quad reduce) ----
        float rm0 = -1e30f, rm1 = -1e30f;
        #pragma unroll
        for (int nt = 0; nt < 8; nt++) {
            rm0 = fmaxf(rm0, fmaxf(s[nt][0], s[nt][1]));
            rm1 = fmaxf(rm1, fmaxf(s[nt][2], s[nt][3]));
        }
        rm0 = fmaxf(rm0, __shfl_xor_sync(0xffffffffu, rm0, 1));
        rm0 = fmaxf(rm0, __shfl_xor_sync(0xffffffffu, rm0, 2));
        rm1 = fmaxf(rm1, __shfl_xor_sync(0xffffffffu, rm1, 1));
        rm1 = fmaxf(rm1, __shfl_xor_sync(0xffffffffu, rm1, 2));

        const float mn0 = fmaxf(m0r, rm0), mn1 = fmaxf(m1r, rm1);
        const float cr0 = __expf(m0r - mn0), cr1 = __expf(m1r - mn1);
        float rs0 = 0.0f, rs1 = 0.0f;
        #pragma unroll
        for (int nt = 0; nt < 8; nt++) {
            s[nt][0] = __expf(s[nt][0] - mn0);
            s[nt][1] = __expf(s[nt][1] - mn0);
            s[nt][2] = __expf(s[nt][2] - mn1);
            s[nt][3] = __expf(s[nt][3] - mn1);
            rs0 += s[nt][0] + s[nt][1];
            rs1 += s[nt][2] + s[nt][3];
        }
        rs0 += __shfl_xor_sync(0xffffffffu, rs0, 1);
        rs0 += __shfl_xor_sync(0xffffffffu, rs0, 2);
        rs1 += __shfl_xor_sync(0xffffffffu, rs1, 1);
        rs1 += __shfl_xor_sync(0xffffffffu, rs1, 2);
        l0 = l0 * cr0 + rs0;  m0r = mn0;
        l1 = l1 * cr1 + rs1;  m1r = mn1;
        #pragma unroll
        for (int nt = 0; nt < 8; nt++) {
            o[nt][0] *= cr0; o[nt][1] *= cr0;
            o[nt][2] *= cr1; o[nt][3] *= cr1;
        }

        // ---- O += P V : C-frag packs into A-frag; V frags via ldmatrix.trans ----
        #pragma unroll
        for (int kb = 0; kb < 4; kb++) {
            const uint32_t a0 = pack_h2(s[2 * kb][0], s[2 * kb][1]);
            const uint32_t a1 = pack_h2(s[2 * kb][2], s[2 * kb][3]);
            const uint32_t a2 = pack_h2(s[2 * kb + 1][0], s[2 * kb + 1][1]);
            const uint32_t a3 = pack_h2(s[2 * kb + 1][2], s[2 * kb + 1][3]);
            uint32_t vf[4][4];
            #pragma unroll
            for (int p = 0; p < 4; p++)
                ldsm_x4_trans(vf[p][0], vf[p][1], vf[p][2], vf[p][3],
                              vbase_b + ((kb * 16 + rV) * RS_A + p * 16 + cV) * 2);
            #pragma unroll
            for (int nt = 0; nt < 8; nt++) {
                const uint32_t b0 = vf[nt >> 1][(nt & 1) * 2];
                const uint32_t b1 = vf[nt >> 1][(nt & 1) * 2 + 1];
                mma_f16(o[nt][0], o[nt][1], o[nt][2], o[nt][3],
                        a0, a1, a2, a3, b0, b1);
            }
        }
    }

    // ---- write normalized output (fp16) to g_att [b, s, h*64 + d] ----
    const float inv0 = 1.0f / l0, inv1 = 1.0f / l1;
    const int b = bh >> 4, h = bh & 15;
    const int row0 = qbase + wrow + grp;
    __half* o0 = g_att + (size_t)(b * SEQ + row0) * DMODEL + h * HD;
    __half* o1 = g_att + (size_t)(b * SEQ + row0 + 8) * DMODEL + h * HD;
    #pragma unroll
    for (int nt = 0; nt < 8; nt++) {
        const int c = nt * 8 + tig * 2;
        *reinterpret_cast<uint32_t*>(o0 + c) = pack_h2(o[nt][0] * inv0, o[nt][1] * inv0);
        *reinterpret_cast<uint32_t*>(o1 + c) = pack_h2(o[nt][2] * inv1, o[nt][3] * inv1);
    }
}

// ===========================================================================
extern "C" void kernel_launch(void* const* d_in, const int* in_sizes, int n_in,
                              void* d_out, int out_size)
{
    const float* x     = (const float*)d_in[0];
    // d_in[1] is the causal mask; causality is implemented directly.
    const float* W_qkv = (const float*)d_in[2];
    const float* b_qkv = (const float*)d_in[3];
    const float* W_o   = (const float*)d_in[4];
    const float* b_o   = (const float*)d_in[5];
    float* out = (float*)d_out;

    cudaFuncSetAttribute(tc_gemm_kernel<0>,
                         cudaFuncAttributeMaxDynamicSharedMemorySize, TC_SMEM_BYTES);
    cudaFuncSetAttribute(tc_gemm_kernel<1>,
                         cudaFuncAttributeMaxDynamicSharedMemorySize, TC_SMEM_BYTES);
    cudaFuncSetAttribute(attn_tc_kernel,
                         cudaFuncAttributeMaxDynamicSharedMemorySize, AT_SMEM_BYTES);

    __half* xt;     cudaGetSymbolAddress((void**)&xt, g_xt);
    __half* wqkv_t; cudaGetSymbolAddress((void**)&wqkv_t, g_wqkv_t);
    __half* wo_t;   cudaGetSymbolAddress((void**)&wo_t, g_wo_t);
    __half* att;    cudaGetSymbolAddress((void**)&att, g_att);

    transpose_h_kernel<<<dim3(N_QKV / 32, GK / 32), dim3(32, 8)>>>(W_qkv, wqkv_t, GK, N_QKV);
    transpose_h_kernel<<<dim3(DMODEL / 32, GK / 32), dim3(32, 8)>>>(W_o, wo_t, GK, DMODEL);
    convert_x_kernel<<<(BATCH * SEQ * GK) / (256 * 4), 256>>>(x, xt);

    tc_gemm_kernel<0><<<dim3(N_QKV / 128, (BATCH * SEQ) / 128), 256, TC_SMEM_BYTES>>>(
        xt, wqkv_t, b_qkv, nullptr);
    attn_tc_kernel<<<(SEQ / 128) * BH, 256, AT_SMEM_BYTES>>>();
    tc_gemm_kernel<1><<<dim3(DMODEL / 128, (BATCH * SEQ) / 128), 256, TC_SMEM_BYTES>>>(
        att, wo_t, b_o, out);
}

// round 14
// speedup vs baseline: 1.1041x; 1.1041x over previous
#include <cuda_runtime.h>
#include <cuda_fp16.h>
#include <cstdint>

#define BATCH 2
#define SEQ 2048
#define DMODEL 1024
#define NH 16
#define HD 64
#define BH (BATCH * NH)
#define N_QKV (3 * DMODEL)
#define GK 1024

// Scratch (allocation-free). All operand buffers are fp16.
__device__ __half g_q[BH * SEQ * HD];          // [bh][s][d], pre-scaled by 0.125
__device__ __half g_k[BH * SEQ * HD];          // [bh][s][d]
__device__ __half g_v[BH * SEQ * HD];          // [bh][s][d]  (row-major)
__device__ __half g_att[BATCH * SEQ * DMODEL]; // attn output
__device__ __half g_xt[BATCH * SEQ * GK];      // X converted
__device__ __half g_wqkv_t[N_QKV * GK];        // [N=3072][K=1024]
__device__ __half g_wo_t[DMODEL * GK];         // [N=1024][K=1024]

__device__ __forceinline__ uint32_t pack_h2(float lo, float hi) {
    __half2 h = __floats2half2_rn(lo, hi);
    return *reinterpret_cast<uint32_t*>(&h);
}

__device__ __forceinline__ void mma_f16(
    float& c0, float& c1, float& c2, float& c3,
    uint32_t a0, uint32_t a1, uint32_t a2, uint32_t a3,
    uint32_t b0, uint32_t b1)
{
    asm volatile(
        "mma.sync.aligned.m16n8k16.row.col.f32.f16.f16.f32 "
        "{%0,%1,%2,%3}, {%4,%5,%6,%7}, {%8,%9}, {%0,%1,%2,%3};"
        : "+f"(c0), "+f"(c1), "+f"(c2), "+f"(c3)
        : "r"(a0), "r"(a1), "r"(a2), "r"(a3), "r"(b0), "r"(b1));
}

__device__ __forceinline__ void ldsm_x4(
    uint32_t& r0, uint32_t& r1, uint32_t& r2, uint32_t& r3, uint32_t saddr)
{
    asm volatile(
        "ldmatrix.sync.aligned.m8n8.x4.shared.b16 {%0,%1,%2,%3}, [%4];"
        : "=r"(r0), "=r"(r1), "=r"(r2), "=r"(r3) : "r"(saddr));
}

__device__ __forceinline__ void ldsm_x4_trans(
    uint32_t& r0, uint32_t& r1, uint32_t& r2, uint32_t& r3, uint32_t saddr)
{
    asm volatile(
        "ldmatrix.sync.aligned.m8n8.x4.trans.shared.b16 {%0,%1,%2,%3}, [%4];"
        : "=r"(r0), "=r"(r1), "=r"(r2), "=r"(r3) : "r"(saddr));
}

__device__ __forceinline__ void cp_async16(uint32_t smem_addr, const void* gptr) {
    asm volatile("cp.async.cg.shared.global [%0], [%1], 16;"
                 :: "r"(smem_addr), "l"(gptr) : "memory");
}
#define CP_COMMIT() asm volatile("cp.async.commit_group;" ::: "memory")
#define CP_WAIT(n)  asm volatile("cp.async.wait_group %0;" :: "n"(n) : "memory")

// ===========================================================================
// Transpose+convert: out[c][r] = h(in[r][c]), in is R x C row-major fp32
// ===========================================================================
__global__ void transpose_h_kernel(const float* __restrict__ in,
                                   __half* __restrict__ out, int R, int C)
{
    __shared__ float t[32][33];
    int c0 = blockIdx.x * 32, r0 = blockIdx.y * 32;
    int x = threadIdx.x, y = threadIdx.y;  // block (32, 8)
    #pragma unroll
    for (int i = 0; i < 32; i += 8)
        t[y + i][x] = in[(size_t)(r0 + y + i) * C + c0 + x];
    __syncthreads();
    #pragma unroll
    for (int i = 0; i < 32; i += 8)
        out[(size_t)(c0 + y + i) * R + r0 + x] = __float2half_rn(t[x][y + i]);
}

// ===========================================================================
// Elementwise convert fp32 -> fp16, vectorized
// ===========================================================================
__global__ void convert_x_kernel(const float* __restrict__ in,
                                 __half* __restrict__ out)
{
    const int i = (blockIdx.x * 256 + threadIdx.x) * 4;
    float4 v = *reinterpret_cast<const float4*>(in + i);
    uint2 u;
    u.x = pack_h2(v.x, v.y);
    u.y = pack_h2(v.z, v.w);
    *reinterpret_cast<uint2*>(out + i) = u;
}

// ===========================================================================
// fp16 mma.sync GEMM, 4-stage cp.async, KC=32, 512 threads / 16 warps.
// CTA 128x128; warp tile m16 x n64 (8M x 2N warps); <=64 regs -> 32 warps/SM.
// EPI 0: scatter q/k/v (packed 32-bit).  EPI 1: fp32 write.
// ===========================================================================
#define KCH 32
#define NKCH (GK / KCH)                  // 32
#define NSTAGE 4
#define RS_H 40                          // smem row stride in halfs (32 + pad)
#define OP_BYTES (128 * RS_H * 2)        // 10240 per operand per stage
#define STAGE_BYTES_G (2 * OP_BYTES)     // 20480 (A then B)
#define TC_SMEM_BYTES (NSTAGE * STAGE_BYTES_G)  // 81920

template<int EPI>
__global__ __launch_bounds__(512, 2) void tc_gemm_kernel(
    const __half* __restrict__ A, const __half* __restrict__ Bt,
    const float* __restrict__ bias, float* __restrict__ C)
{
    extern __shared__ uint32_t sm[];
    uint32_t smb;
    asm("{ .reg .u64 t; cvta.to.shared.u64 t, %1; cvt.u32.u64 %0, t; }"
        : "=r"(smb) : "l"(sm));

    const int tid = threadIdx.x;
    const int wid = tid >> 5, lane = tid & 31;
    const int grp = lane >> 2, tig = lane & 3;
    const int wm = wid >> 1, wn = wid & 1;     // 8 x 2 warps
    const int m0 = blockIdx.y * 128;
    const int n0 = blockIdx.x * 128;

    const __half* Ag = A + (size_t)m0 * GK;
    const __half* Bg = Bt + (size_t)n0 * GK;

    // ldmatrix per-lane row/col mapping
    const int lt = lane >> 3, le = lane & 7;
    const int rA = le + (lt & 1) * 8;          // A: (m8, m8+8) x (k0-7, k8-15)
    const int cA = (lt >> 1) * 8;
    const int rB = le + (lt >> 1) * 8;         // B: (n8, n8+8) x (k0-7, k8-15)
    const int cB = (lt & 1) * 8;

    // cp.async coords: 128 rows x 64B per operand per chunk; 1x16B per thread
    const int lr = tid >> 2;            // row 0..127
    const int lc = tid & 3;             // 16B chunk 0..3

    float acc[8][4];
    #pragma unroll
    for (int j = 0; j < 8; j++)
        #pragma unroll
        for (int q = 0; q < 4; q++) acc[j][q] = 0.0f;

    // prologue: chunks 0..NSTAGE-2 into stages 0..NSTAGE-2 (one group each)
    #pragma unroll
    for (int p = 0; p < NSTAGE - 1; p++) {
        const uint32_t asmp = smb + p * STAGE_BYTES_G;
        const uint32_t bsmp = asmp + OP_BYTES;
        const __half* ap = Ag + p * KCH;
        const __half* bp = Bg + p * KCH;
        cp_async16(asmp + (lr * RS_H + lc * 8) * 2, ap + (size_t)lr * GK + lc * 8);
        cp_async16(bsmp + (lr * RS_H + lc * 8) * 2, bp + (size_t)lr * GK + lc * 8);
        CP_COMMIT();
    }

    for (int kc = 0; kc < NKCH; kc++) {
        if (kc < NKCH - NSTAGE + 1) { CP_WAIT(NSTAGE - 2); }
        else                        { CP_WAIT(0); }
        __syncthreads();   // chunk kc visible; compute kc-1 done by all warps

        // prefetch chunk kc+NSTAGE-1 into its stage (freed by barrier above)
        if (kc + NSTAGE - 1 < NKCH) {
            const int st = (kc + NSTAGE - 1) % NSTAGE;
            const uint32_t asmx = smb + st * STAGE_BYTES_G;
            const uint32_t bsmx = asmx + OP_BYTES;
            const __half* an = Ag + (kc + NSTAGE - 1) * KCH;
            const __half* bn = Bg + (kc + NSTAGE - 1) * KCH;
            cp_async16(asmx + (lr * RS_H + lc * 8) * 2, an + (size_t)lr * GK + lc * 8);
            cp_async16(bsmx + (lr * RS_H + lc * 8) * 2, bn + (size_t)lr * GK + lc * 8);
            CP_COMMIT();
        }

        const uint32_t abase = smb + (kc % NSTAGE) * STAGE_BYTES_G;
        const uint32_t bbase = abase + OP_BYTES;

        #pragma unroll
        for (int ks = 0; ks < 2; ks++) {          // 2 x k16 per KC=32
            const int kh = ks * 16;               // half offset
            uint32_t a0, a1, a2, a3;
            ldsm_x4(a0, a1, a2, a3,
                    abase + ((wm * 16 + rA) * RS_H + kh + cA) * 2);
            #pragma unroll
            for (int p = 0; p < 4; p++) {
                uint32_t b0, b1, b2, b3;
                ldsm_x4(b0, b1, b2, b3,
                        bbase + ((wn * 64 + p * 16 + rB) * RS_H + kh + cB) * 2);
                mma_f16(acc[2 * p][0], acc[2 * p][1], acc[2 * p][2], acc[2 * p][3],
                        a0, a1, a2, a3, b0, b1);
                mma_f16(acc[2 * p + 1][0], acc[2 * p + 1][1],
                        acc[2 * p + 1][2], acc[2 * p + 1][3],
                        a0, a1, a2, a3, b2, b3);
            }
        }
    }

    #pragma unroll
    for (int half = 0; half < 2; half++) {
        const int m = m0 + wm * 16 + grp + half * 8;
        #pragma unroll
        for (int nt = 0; nt < 8; nt++) {
            const int n = n0 + wn * 64 + nt * 8 + tig * 2;   // even; n,n+1 pair
            const float v0 = acc[nt][half * 2 + 0] + __ldg(&bias[n]);
            const float v1 = acc[nt][half * 2 + 1] + __ldg(&bias[n + 1]);
            if (EPI == 0) {
                const int b = m >> 11;
                const int srow = m & (SEQ - 1);
                const int h = n / 192;
                const int r = n - h * 192;
                const int which = r >> 6;
                const int dd = r & 63;                      // even
                const int bh = b * NH + h;
                const size_t idx = ((size_t)bh * SEQ + srow) * HD + dd;
                if (which == 0)
                    *reinterpret_cast<uint32_t*>(&g_q[idx]) =
                        pack_h2(v0 * 0.125f, v1 * 0.125f);
                else if (which == 1)
                    *reinterpret_cast<uint32_t*>(&g_k[idx]) = pack_h2(v0, v1);
                else
                    *reinterpret_cast<uint32_t*>(&g_v[idx]) = pack_h2(v0, v1);
            } else {
                *reinterpret_cast<float2*>(&C[(size_t)m * DMODEL + n]) =
                    make_float2(v0, v1);
            }
        }
    }
}

// ===========================================================================
// fp16 tensor-core causal flash attention, 3-stage cp.async K/V pipeline,
// ldmatrix fragments (V via ldmatrix.trans from row-major [s][d]).
// (Unchanged from round 13.)
// ===========================================================================
#define RS_A 72                            // smem row stride in halfs
#define AT_OP_BYTES (64 * RS_A * 2)        // 9216 per operand tile
#define AT_PAIR_BYTES (2 * AT_OP_BYTES)    // K then V = 18432 per stage
#define NSTAGE_A 3
#define AT_SMEM_BYTES (NSTAGE_A * AT_PAIR_BYTES)  // 55296

__global__ __launch_bounds__(256, 2) void attn_tc_kernel()
{
    extern __shared__ uint32_t sm[];
    uint32_t smb;
    asm("{ .reg .u64 t; cvta.to.shared.u64 t, %1; cvt.u32.u64 %0, t; }"
        : "=r"(smb) : "l"(sm));

    const int tid = threadIdx.x;
    const int wid = tid >> 5, lane = tid & 31;
    const int grp = lane >> 2, tig = lane & 3;
    const int bid = blockIdx.x;
    const int qt = (SEQ / 128 - 1) - (bid >> 5);   // heavy tiles first
    const int bh = bid & 31;
    const int qbase = qt * 128;
    const int wrow = wid * 16;

    const __half* __restrict__ Qu = g_q + ((size_t)bh * SEQ + qbase + wrow) * HD;
    const __half* __restrict__ Ku = g_k + (size_t)bh * SEQ * HD;
    const __half* __restrict__ Vu = g_v + (size_t)bh * SEQ * HD;   // [s][d]

    // ldmatrix lane mappings
    const int lt = lane >> 3, le = lane & 7;
    const int rB = le + (lt >> 1) * 8;             // K (non-trans): n-rows
    const int cB = (lt & 1) * 8;
    const int rV = (lt & 1) * 8 + le;              // V (trans): s-rows (k dim)
    const int cV = (lt >> 1) * 8;                  // d-cols (n dim)

    // ---- Q fragments straight from global (fp16, pre-scaled) ----
    uint32_t aq[4][4];
    #pragma unroll
    for (int kb = 0; kb < 4; kb++) {
        aq[kb][0] = *reinterpret_cast<const uint32_t*>(Qu + grp * HD + kb * 16 + 2 * tig);
        aq[kb][1] = *reinterpret_cast<const uint32_t*>(Qu + (grp + 8) * HD + kb * 16 + 2 * tig);
        aq[kb][2] = *reinterpret_cast<const uint32_t*>(Qu + grp * HD + kb * 16 + 8 + 2 * tig);
        aq[kb][3] = *reinterpret_cast<const uint32_t*>(Qu + (grp + 8) * HD + kb * 16 + 8 + 2 * tig);
    }

    float o[8][4];
    #pragma unroll
    for (int nt = 0; nt < 8; nt++)
        #pragma unroll
        for (int q = 0; q < 4; q++) o[nt][q] = 0.0f;
    float m0r = -1e30f, m1r = -1e30f, l0 = 0.0f, l1 = 0.0f;

    const int nkt = 2 * qt + 2;

    // cp.async coords: 64 rows x 128B per operand; 2x16B per thread per operand
    const int cr = tid >> 2;            // row 0..63
    const int ca = tid & 3;             // chunks ca and ca+4

    // prologue: tiles 0..NSTAGE_A-2 (nkt >= 2 always)
    #pragma unroll
    for (int p = 0; p < NSTAGE_A - 1; p++) {
        const uint32_t ksm = smb + p * AT_PAIR_BYTES;
        const uint32_t vsm = ksm + AT_OP_BYTES;
        const __half* kg = Ku + (size_t)p * 64 * HD;
        const __half* vg = Vu + (size_t)p * 64 * HD;
        #pragma unroll
        for (int i = 0; i < 2; i++) {
            const int c = ca + i * 4;
            cp_async16(ksm + (cr * RS_A + c * 8) * 2, kg + (size_t)cr * HD + c * 8);
            cp_async16(vsm + (cr * RS_A + c * 8) * 2, vg + (size_t)cr * HD + c * 8);
        }
        CP_COMMIT();
    }

    for (int kt = 0; kt < nkt; kt++) {
        if (kt < nkt - 1) { CP_WAIT(NSTAGE_A - 2); }
        else              { CP_WAIT(0); }
        __syncthreads();   // tile kt resident; compute kt-1 done by all warps

        if (kt + NSTAGE_A - 1 < nkt) {
            const int st = (kt + NSTAGE_A - 1) % NSTAGE_A;
            const uint32_t ksm = smb + st * AT_PAIR_BYTES;
            const uint32_t vsm = ksm + AT_OP_BYTES;
            const __half* kg = Ku + (size_t)(kt + NSTAGE_A - 1) * 64 * HD;
            const __half* vg = Vu + (size_t)(kt + NSTAGE_A - 1) * 64 * HD;
            #pragma unroll
            for (int i = 0; i < 2; i++) {
                const int c = ca + i * 4;
                cp_async16(ksm + (cr * RS_A + c * 8) * 2, kg + (size_t)cr * HD + c * 8);
                cp_async16(vsm + (cr * RS_A + c * 8) * 2, vg + (size_t)cr * HD + c * 8);
            }
            CP_COMMIT();
        }

        const uint32_t kbase_b = smb + (kt % NSTAGE_A) * AT_PAIR_BYTES;
        const uint32_t vbase_b = kbase_b + AT_OP_BYTES;

        // ---- S = Q K^T : 4 k16-blocks x 8 n-tiles ----
        float s[8][4];
        #pragma unroll
        for (int nt = 0; nt < 8; nt++)
            #pragma unroll
            for (int q = 0; q < 4; q++) s[nt][q] = 0.0f;

        #pragma unroll
        for (int kb = 0; kb < 4; kb++) {
            uint32_t kf[4][4];
            #pragma unroll
            for (int p = 0; p < 4; p++)
                ldsm_x4(kf[p][0], kf[p][1], kf[p][2], kf[p][3],
                        kbase_b + ((p * 16 + rB) * RS_A + kb * 16 + cB) * 2);
            #pragma unroll
            for (int nt = 0; nt < 8; nt++) {
                const uint32_t b0 = kf[nt >> 1][(nt & 1) * 2];
                const uint32_t b1 = kf[nt >> 1][(nt & 1) * 2 + 1];
                mma_f16(s[nt][0], s[nt][1], s[nt][2], s[nt][3],
                        aq[kb][0], aq[kb][1], aq[kb][2], aq[kb][3], b0, b1);
            }
        }

        // ---- causal mask (last two tiles only) ----
        if (kt >= 2 * qt) {
            const int row0 = qbase + wrow + grp;
            const int colb = kt * 64 + tig * 2;
            #pragma unroll
            for (int nt = 0; nt < 8; nt++) {
                const int c = colb + nt * 8;
                if (c > row0)         s[nt][0] = -1e30f;
                if (c + 1 > row0)     s[nt][1] = -1e30f;
                if (c > row0 + 8)     s[nt][2] = -1e30f;
                if (c + 1 > row0 + 8) s[nt][3] = -1e30f;
            }
        }

        // ---- online softmax (2 rows per thread, quad reduce) ----
        float rm0 = -1e30f, rm1 = -1e30f;
        #pragma unroll
        for (int nt = 0; nt < 8; nt++) {
            rm0 = fmaxf(rm0, fmaxf(s[nt][0], s[nt][1]));
            rm1 = fmaxf(rm1, fmaxf(s[nt][2], s[nt][3]));
        }
        rm0 = fmaxf(rm0, __shfl_xor_sync(0xffffffffu, rm0, 1));
        rm0 = fmaxf(rm0, __shfl_xor_sync(0xffffffffu, rm0, 2));
        rm1 = fmaxf(rm1, __shfl_xor_sync(0xffffffffu, rm1, 1));
        rm1 = fmaxf(rm1, __shfl_xor_sync(0xffffffffu, rm1, 2));

        const float mn0 = fmaxf(m0r, rm0), mn1 = fmaxf(m1r, rm1);
        const float cr0 = __expf(m0r - mn0), cr1 = __expf(m1r - mn1);
        float rs0 = 0.0f, rs1 = 0.0f;
        #pragma unroll
        for (int nt = 0; nt < 8; nt++) {
            s[nt][0] = __expf(s[nt][0] - mn0);
            s[nt][1] = __expf(s[nt][1] - mn0);
            s[nt][2] = __expf(s[nt][2] - mn1);
            s[nt][3] = __expf(s[nt][3] - mn1);
            rs0 += s[nt][0] + s[nt][1];
            rs1 += s[nt][2] + s[nt][3];
        }
        rs0 += __shfl_xor_sync(0xffffffffu, rs0, 1);
        rs0 += __shfl_xor_sync(0xffffffffu, rs0, 2);
        rs1 += __shfl_xor_sync(0xffffffffu, rs1, 1);
        rs1 += __shfl_xor_sync(0xffffffffu, rs1, 2);
        l0 = l0 * cr0 + rs0;  m0r = mn0;
        l1 = l1 * cr1 + rs1;  m1r = mn1;
        #pragma unroll
        for (int nt = 0; nt < 8; nt++) {
            o[nt][0] *= cr0; o[nt][1] *= cr0;
            o[nt][2] *= cr1; o[nt][3] *= cr1;
        }

        // ---- O += P V : C-frag packs into A-frag; V frags via ldmatrix.trans ----
        #pragma unroll
        for (int kb = 0; kb < 4; kb++) {
            const uint32_t a0 = pack_h2(s[2 * kb][0], s[2 * kb][1]);
            const uint32_t a1 = pack_h2(s[2 * kb][2], s[2 * kb][3]);
            const uint32_t a2 = pack_h2(s[2 * kb + 1][0], s[2 * kb + 1][1]);
            const uint32_t a3 = pack_h2(s[2 * kb + 1][2], s[2 * kb + 1][3]);
            uint32_t vf[4][4];
            #pragma unroll
            for (int p = 0; p < 4; p++)
                ldsm_x4_trans(vf[p][0], vf[p][1], vf[p][2], vf[p][3],
                              vbase_b + ((kb * 16 + rV) * RS_A + p * 16 + cV) * 2);
            #pragma unroll
            for (int nt = 0; nt < 8; nt++) {
                const uint32_t b0 = vf[nt >> 1][(nt & 1) * 2];
                const uint32_t b1 = vf[nt >> 1][(nt & 1) * 2 + 1];
                mma_f16(o[nt][0], o[nt][1], o[nt][2], o[nt][3],
                        a0, a1, a2, a3, b0, b1);
            }
        }
    }

    // ---- write normalized output (fp16) to g_att [b, s, h*64 + d] ----
    const float inv0 = 1.0f / l0, inv1 = 1.0f / l1;
    const int b = bh >> 4, h = bh & 15;
    const int row0 = qbase + wrow + grp;
    __half* o0 = g_att + (size_t)(b * SEQ + row0) * DMODEL + h * HD;
    __half* o1 = g_att + (size_t)(b * SEQ + row0 + 8) * DMODEL + h * HD;
    #pragma unroll
    for (int nt = 0; nt < 8; nt++) {
        const int c = nt * 8 + tig * 2;
        *reinterpret_cast<uint32_t*>(o0 + c) = pack_h2(o[nt][0] * inv0, o[nt][1] * inv0);
        *reinterpret_cast<uint32_t*>(o1 + c) = pack_h2(o[nt][2] * inv1, o[nt][3] * inv1);
    }
}

// ===========================================================================
extern "C" void kernel_launch(void* const* d_in, const int* in_sizes, int n_in,
                              void* d_out, int out_size)
{
    const float* x     = (const float*)d_in[0];
    // d_in[1] is the causal mask; causality is implemented directly.
    const float* W_qkv = (const float*)d_in[2];
    const float* b_qkv = (const float*)d_in[3];
    const float* W_o   = (const float*)d_in[4];
    const float* b_o   = (const float*)d_in[5];
    float* out = (float*)d_out;

    cudaFuncSetAttribute(tc_gemm_kernel<0>,
                         cudaFuncAttributeMaxDynamicSharedMemorySize, TC_SMEM_BYTES);
    cudaFuncSetAttribute(tc_gemm_kernel<1>,
                         cudaFuncAttributeMaxDynamicSharedMemorySize, TC_SMEM_BYTES);
    cudaFuncSetAttribute(attn_tc_kernel,
                         cudaFuncAttributeMaxDynamicSharedMemorySize, AT_SMEM_BYTES);

    __half* xt;     cudaGetSymbolAddress((void**)&xt, g_xt);
    __half* wqkv_t; cudaGetSymbolAddress((void**)&wqkv_t, g_wqkv_t);
    __half* wo_t;   cudaGetSymbolAddress((void**)&wo_t, g_wo_t);
    __half* att;    cudaGetSymbolAddress((void**)&att, g_att);

    transpose_h_kernel<<<dim3(N_QKV / 32, GK / 32), dim3(32, 8)>>>(W_qkv, wqkv_t, GK, N_QKV);
    transpose_h_kernel<<<dim3(DMODEL / 32, GK / 32), dim3(32, 8)>>>(W_o, wo_t, GK, DMODEL);
    convert_x_kernel<<<(BATCH * SEQ * GK) / (256 * 4), 256>>>(x, xt);

    tc_gemm_kernel<0><<<dim3(N_QKV / 128, (BATCH * SEQ) / 128), 512, TC_SMEM_BYTES>>>(
        xt, wqkv_t, b_qkv, nullptr);
    attn_tc_kernel<<<(SEQ / 128) * BH, 256, AT_SMEM_BYTES>>>();
    tc_gemm_kernel<1><<<dim3(DMODEL / 128, (BATCH * SEQ) / 128), 512, TC_SMEM_BYTES>>>(
        att, wo_t, b_o, out);
}